// round 1
// baseline (speedup 1.0000x reference)
#include <cuda_runtime.h>
#include <cstdint>

// Problem constants
#define Bb 8
#define Hh 4
#define Nn 2048
#define DM 256
#define DH 64

typedef unsigned long long u64;

// ---------------- scratch (device globals: no allocation allowed) ----------
__device__ float g_q [Bb*Hh*Nn*DH];   // [b][h][n][dh]
__device__ float g_kr[Bb*Hh*Nn*DH];   // k-proj + r-proj
__device__ float g_v [Bb*Hh*Nn*DH];
__device__ float g_x [Bb*Nn*DM];      // concat-head attention output [b][n][h*64+dh]

// ---------------- f32x2 packed math helpers --------------------------------
__device__ __forceinline__ u64 pack2(float lo, float hi){
    u64 r; asm("mov.b64 %0, {%1, %2};" : "=l"(r) : "f"(lo), "f"(hi)); return r;
}
__device__ __forceinline__ float2 unpack2(u64 v){
    float2 r; asm("mov.b64 {%0, %1}, %2;" : "=f"(r.x), "=f"(r.y) : "l"(v)); return r;
}
#define FMA2(d,a,b) asm("fma.rn.f32x2 %0, %1, %2, %0;" : "+l"(d) : "l"(a), "l"(b))
#define MUL2(d,a,b) asm("mul.rn.f32x2 %0, %1, %2;" : "=l"(d) : "l"(a), "l"(b))

// Fast exp on the FMA pipe (avoids MUFU.EX2 throughput wall).
// exp(x) = 2^(x*log2e); round via magic constant; degree-5 poly for 2^f, f in [-0.5,0.5].
__device__ __forceinline__ float fast_exp(float x){
    x = fmaxf(x, -87.0f);
    float y = x * 1.4426950408889634f;
    float z = y + 12582912.0f;          // round-to-nearest integer (|y| << 2^22)
    float n = z - 12582912.0f;
    float f = y - n;                    // [-0.5, 0.5]
    float p = 1.3333558146e-3f;
    p = fmaf(p, f, 9.6181291076e-3f);
    p = fmaf(p, f, 5.5504108664e-2f);
    p = fmaf(p, f, 2.4022650696e-1f);
    p = fmaf(p, f, 6.9314718056e-1f);
    p = fmaf(p, f, 1.0f);
    int zi = __float_as_int(z);         // = 0x4B400000 + round(y)
    float sc = __int_as_float((zi - 0x4B400000 + 127) << 23);  // 2^round(y)
    return p * sc;
}

// ---------------- projection / output GEMM ---------------------------------
// C[M=16384, 256cols] = A @ W (+ optional A2 @ W2) + bias(+bias2)
// mode 0: W layout [H][256][64] (per-head proj), nb = head, dst = scratch [b][h][n][64]
// mode 1: W layout [out][in] (Wo), A = g_x, nb = 64-col block, dst = Cout [m][256]
#define BM 128
#define BN 64
#define BK 32

__global__ void __launch_bounds__(256) gemm_kernel(
    const float* __restrict__ A1, const float* __restrict__ W1,
    const float* __restrict__ A2, const float* __restrict__ W2,
    const float* __restrict__ b1, const float* __restrict__ b2,
    int mode, int dsel, float* __restrict__ Cout)
{
    __shared__ __align__(16) float As[BK][BM+4];
    __shared__ __align__(16) float Ws[BK][BN+4];
    const int tid = threadIdx.x;
    const int tx = tid & 15, ty = tid >> 4;
    const int m0 = blockIdx.x * BM;
    const int nb = blockIdx.y;

    u64 acc[4][4];
#pragma unroll
    for (int i = 0; i < 4; i++)
#pragma unroll
        for (int j = 0; j < 4; j++) acc[i][j] = 0ull;

    const int nsrc = (A2 != nullptr) ? 2 : 1;
    for (int s = 0; s < nsrc; s++) {
        const float* A = s ? A2 : A1;
        const float* W = s ? W2 : W1;
        if (mode == 1) A = g_x;
        for (int kc = 0; kc < DM; kc += BK) {
            __syncthreads();
            // A tile, stored transposed As[k][m]
#pragma unroll
            for (int i = 0; i < 4; i++) {
                int idx = i * 256 + tid;
                int row = idx >> 3, kq = idx & 7;
                float4 v = *(const float4*)(A + (size_t)(m0 + row) * DM + kc + kq * 4);
                As[kq*4+0][row] = v.x; As[kq*4+1][row] = v.y;
                As[kq*4+2][row] = v.z; As[kq*4+3][row] = v.w;
            }
            // W tile Ws[k][n]
            if (mode == 0) {
#pragma unroll
                for (int i = 0; i < 2; i++) {
                    int idx = i * 256 + tid;
                    int wk = idx >> 4, nq = idx & 15;
                    *(float4*)&Ws[wk][nq*4] =
                        *(const float4*)(W + (size_t)nb * (DM*DH) + (size_t)(kc + wk) * DH + nq * 4);
                }
            } else {
#pragma unroll
                for (int i = 0; i < 2; i++) {
                    int idx = i * 256 + tid;
                    int n = idx >> 3, kq = idx & 7;
                    float4 v = *(const float4*)(W + (size_t)(nb * 64 + n) * DM + kc + kq * 4);
                    Ws[kq*4+0][n] = v.x; Ws[kq*4+1][n] = v.y;
                    Ws[kq*4+2][n] = v.z; Ws[kq*4+3][n] = v.w;
                }
            }
            __syncthreads();
#pragma unroll
            for (int kk = 0; kk < BK; kk++) {
                ulonglong2 a01 = *(const ulonglong2*)&As[kk][ty*8];
                ulonglong2 a23 = *(const ulonglong2*)&As[kk][ty*8+4];
                u64 av[4] = {a01.x, a01.y, a23.x, a23.y};
                float4 bf = *(const float4*)&Ws[kk][tx*4];
                u64 bb[4] = {pack2(bf.x,bf.x), pack2(bf.y,bf.y),
                             pack2(bf.z,bf.z), pack2(bf.w,bf.w)};
#pragma unroll
                for (int r = 0; r < 4; r++)
#pragma unroll
                    for (int c = 0; c < 4; c++)
                        FMA2(acc[r][c], av[r], bb[c]);
            }
        }
    }

    // bias
    float4 bias = *(const float4*)(b1 + nb * 64 + tx * 4);
    if (b2) {
        float4 t2 = *(const float4*)(b2 + nb * 64 + tx * 4);
        bias.x += t2.x; bias.y += t2.y; bias.z += t2.z; bias.w += t2.w;
    }
    float* dst0 = (dsel == 0) ? g_q : (dsel == 1) ? g_kr : g_v;

#pragma unroll
    for (int r = 0; r < 4; r++) {
        float2 u0 = unpack2(acc[r][0]), u1 = unpack2(acc[r][1]);
        float2 u2 = unpack2(acc[r][2]), u3 = unpack2(acc[r][3]);
        float4 ev = make_float4(u0.x + bias.x, u1.x + bias.y, u2.x + bias.z, u3.x + bias.w);
        float4 ov = make_float4(u0.y + bias.x, u1.y + bias.y, u2.y + bias.z, u3.y + bias.w);
        int mrow = m0 + ty * 8 + r * 2;
        if (mode == 0) {
            int bi = mrow >> 11, ni = mrow & (Nn - 1);
            *(float4*)(dst0 + (((size_t)bi * Hh + nb) * Nn + ni) * DH + tx * 4) = ev;
            bi = (mrow + 1) >> 11; ni = (mrow + 1) & (Nn - 1);
            *(float4*)(dst0 + (((size_t)bi * Hh + nb) * Nn + ni) * DH + tx * 4) = ov;
        } else {
            *(float4*)(Cout + (size_t)mrow * DM + nb * 64 + tx * 4) = ev;
            *(float4*)(Cout + (size_t)(mrow + 1) * DM + nb * 64 + tx * 4) = ov;
        }
    }
}

// ---------------- fused attention (scores out + online softmax + O) --------
// Block: 128 q-rows, 128 threads (1 row/thread). Loop over 64-key tiles.
// q-row & O-accumulator register-resident as f32x2; K+R / V tiles in smem
// (broadcast LDS.128); scores staged in pad-65 smem for coalesced STG.
__global__ void __launch_bounds__(128) attn_kernel(float* __restrict__ scores)
{
    extern __shared__ __align__(16) float smem[];
    float* krs  = smem;               // 64*64
    float* vsm  = smem + 64 * 64;     // 64*64
    float* srow = smem + 2 * 64 * 64; // 128*65

    const int tid = threadIdx.x;
    const int b = blockIdx.z, h = blockIdx.y;
    const int q0 = blockIdx.x * 128;
    const int qi = q0 + tid;
    const size_t bh = (size_t)(b * Hh + h);
    const float* qp  = g_q  + (bh * Nn + qi) * DH;
    const float* krb = g_kr + bh * Nn * DH;
    const float* vb  = g_v  + bh * Nn * DH;
    float* sb = scores + (bh * Nn + q0) * Nn;

    u64 q2[32], o2[32];
#pragma unroll
    for (int i = 0; i < 16; i++) {
        ulonglong2 t = ((const ulonglong2*)qp)[i];
        q2[2*i] = t.x; q2[2*i+1] = t.y;
    }
#pragma unroll
    for (int i = 0; i < 32; i++) o2[i] = 0ull;

    float mrun = -1e30f, lrun = 0.f;
    float* myrow = srow + tid * 65;

    for (int kt = 0; kt < Nn; kt += 64) {
        __syncthreads();
        // cooperative tile load (coalesced float4)
        const float4* ks4 = (const float4*)(krb + (size_t)kt * DH);
        const float4* vv4 = (const float4*)(vb  + (size_t)kt * DH);
#pragma unroll
        for (int i = 0; i < 8; i++) {
            int idx = i * 128 + tid;
            ((float4*)krs)[idx] = ks4[idx];
            ((float4*)vsm)[idx] = vv4[idx];
        }
        __syncthreads();

        // scores for my row vs 64 keys
        float tmax = -1e30f;
#pragma unroll 2
        for (int j = 0; j < 64; j++) {
            u64 a0 = 0ull, a1 = 0ull;
            const ulonglong2* kp = (const ulonglong2*)(krs + j * 64);
#pragma unroll
            for (int d = 0; d < 16; d++) {
                ulonglong2 kk = kp[d];
                FMA2(a0, q2[2*d],   kk.x);
                FMA2(a1, q2[2*d+1], kk.y);
            }
            float2 f0 = unpack2(a0), f1 = unpack2(a1);
            float s = ((f0.x + f1.x) + (f0.y + f1.y)) * 0.125f;  // 1/sqrt(64)
            tmax = fmaxf(tmax, s);
            myrow[j] = s;
        }
        __syncthreads();

        // coalesced pre-softmax score write (pad-65 rows: conflict-free)
        {
            float* sg = sb + kt;
#pragma unroll 4
            for (int i = 0; i < 64; i++) {
                int idx = i * 128 + tid;
                int r = idx >> 6, c = idx & 63;
                sg[(size_t)r * Nn + c] = srow[r * 65 + c];
            }
        }

        // online softmax merge + O accumulation
        float mnew = fmaxf(mrun, tmax);
        float corr = fast_exp(mrun - mnew);
        u64 c2 = pack2(corr, corr);
#pragma unroll
        for (int i = 0; i < 32; i++) MUL2(o2[i], o2[i], c2);
        float lsum = 0.f;
#pragma unroll 2
        for (int j = 0; j < 64; j++) {
            float p = fast_exp(myrow[j] - mnew);
            lsum += p;
            u64 pp = pack2(p, p);
            const ulonglong2* vp = (const ulonglong2*)(vsm + j * 64);
#pragma unroll
            for (int d = 0; d < 16; d++) {
                ulonglong2 vv = vp[d];
                FMA2(o2[2*d],   pp, vv.x);
                FMA2(o2[2*d+1], pp, vv.y);
            }
        }
        lrun = lrun * corr + lsum;
        mrun = mnew;
    }

    float inv = 1.0f / lrun;
    float* xo = g_x + (size_t)(b * Nn + qi) * DM + h * DH;
#pragma unroll
    for (int i = 0; i < 16; i++) {
        float2 u = unpack2(o2[2*i]), w = unpack2(o2[2*i+1]);
        *(float4*)(xo + i * 4) = make_float4(u.x * inv, u.y * inv, w.x * inv, w.y * inv);
    }
}

// ---------------- launch ----------------------------------------------------
extern "C" void kernel_launch(void* const* d_in, const int* in_sizes, int n_in,
                              void* d_out, int out_size)
{
    (void)in_sizes; (void)n_in; (void)out_size;
    const float* Q  = (const float*)d_in[0];
    const float* K  = (const float*)d_in[1];
    const float* V  = (const float*)d_in[2];
    const float* R  = (const float*)d_in[3];
    const float* Wq = (const float*)d_in[4];
    const float* bq = (const float*)d_in[5];
    const float* Wk = (const float*)d_in[6];
    const float* bk = (const float*)d_in[7];
    const float* Wv = (const float*)d_in[8];
    const float* bv = (const float*)d_in[9];
    const float* Wr = (const float*)d_in[10];
    const float* br = (const float*)d_in[11];
    const float* Wo = (const float*)d_in[12];
    const float* bo = (const float*)d_in[13];

    float* outp   = (float*)d_out;                       // [B,N,256]
    float* scores = outp + (size_t)Bb * Nn * DM;         // [B,H,N,N]

    dim3 gg(Nn * Bb / BM, Hh);   // 128 x 4

    // projections: q, (k+r), v
    gemm_kernel<<<gg, 256>>>(Q, Wq, nullptr, nullptr, bq, nullptr, 0, 0, nullptr);
    gemm_kernel<<<gg, 256>>>(K, Wk, R, Wr, bk, br, 0, 1, nullptr);
    gemm_kernel<<<gg, 256>>>(V, Wv, nullptr, nullptr, bv, nullptr, 0, 2, nullptr);

    // fused attention
    int smem_bytes = (64 * 64 + 64 * 64 + 128 * 65) * (int)sizeof(float);  // 66048
    cudaFuncSetAttribute(attn_kernel, cudaFuncAttributeMaxDynamicSharedMemorySize, smem_bytes);
    dim3 ga(Nn / 128, Hh, Bb);   // 16 x 4 x 8
    attn_kernel<<<ga, 128, smem_bytes>>>(scores);

    // output projection
    gemm_kernel<<<gg, 256>>>(nullptr, Wo, nullptr, nullptr, bo, nullptr, 1, 3, outp);
}